// round 5
// baseline (speedup 1.0000x reference)
#include <cuda_runtime.h>
#include <cuda_bf16.h>

#define N_NODES 250000
#define N_EDGES 5000000

// Scratch (device globals — no allocation allowed)
__device__ int    g_idx_is64;        // 1 if edge_index is int64, 0 if int32
__device__ int    g_deg[N_NODES];
__device__ float  g_dinv[N_NODES];
__device__ float  g_y[N_NODES];      // x[i] * dinv[i]
__device__ float  g_s1[N_NODES];     // layer-1 scatter accumulator
__device__ float2 g_t[N_NODES];      // per-node layer-2 message (z * dinv)
__device__ float2 g_oacc[N_NODES];   // layer-2 scatter accumulator

// ---- dtype detection: int64 edges have zero high words at odd positions ----
__global__ void k_detect(const int* __restrict__ ei32) {
    __shared__ int s_or;
    if (threadIdx.x == 0) s_or = 0;
    __syncthreads();
    // words 1,3,...,255 are safely within the buffer under both interpretations
    int v = ei32[2 * threadIdx.x + 1];
    if (v != 0) atomicOr(&s_or, 1);
    __syncthreads();
    if (threadIdx.x == 0) g_idx_is64 = (s_or == 0) ? 1 : 0;
}

__device__ __forceinline__ int load_idx(const void* __restrict__ base,
                                        long long i, int is64) {
    if (is64) return (int)((const long long*)base)[i];
    return ((const int*)base)[i];
}

__global__ void k_init_deg() {
    int i = blockIdx.x * blockDim.x + threadIdx.x;
    if (i < N_NODES) g_deg[i] = 0;
}

// Degree pass: count in-degree from col
__global__ void k_edge_deg(const void* __restrict__ ei) {
    int i = blockIdx.x * blockDim.x + threadIdx.x;
    if (i < N_EDGES) {
        int is64 = g_idx_is64;
        int c = load_idx(ei, (long long)N_EDGES + i, is64);
        atomicAdd(&g_deg[c], 1);
    }
}

// Per-node: dinv = rsqrt(indeg + 1 self-loop); y = x*dinv; init s1 with self-loop term.
__global__ void k_node_a(const float* __restrict__ x) {
    int i = blockIdx.x * blockDim.x + threadIdx.x;
    if (i < N_NODES) {
        float d = rsqrtf((float)(g_deg[i] + 1));
        g_dinv[i] = d;
        float y = x[i] * d;
        g_y[i] = y;
        g_s1[i] = y;   // self-loop; final multiply by dinv[c] happens in k_node_b
    }
}

// Layer-1 scatter: s1_acc[col] += y[row]
__global__ void k_edge_pass2(const void* __restrict__ ei) {
    int i = blockIdx.x * blockDim.x + threadIdx.x;
    if (i < N_EDGES) {
        int is64 = g_idx_is64;
        int r = load_idx(ei, i, is64);
        int c = load_idx(ei, (long long)N_EDGES + i, is64);
        atomicAdd(&g_s1[c], g_y[r]);
    }
}

// Per-node MLP: s1 -> relu(W1*s1 + b1) -> @W2 -> scale by dinv; init layer-2 acc (self-loop)
__global__ void k_node_b(const float* __restrict__ W1,
                         const float* __restrict__ b1,
                         const float* __restrict__ W2) {
    __shared__ float sW1[16], sB1[16], sW2[32];
    int t = threadIdx.x;
    if (t < 16) { sW1[t] = W1[t]; sB1[t] = b1[t]; }
    else if (t < 48) { sW2[t - 16] = W2[t - 16]; }
    __syncthreads();

    int i = blockIdx.x * blockDim.x + threadIdx.x;
    if (i < N_NODES) {
        float d = g_dinv[i];
        float s = d * g_s1[i];
        float z0 = 0.f, z1 = 0.f;
        #pragma unroll
        for (int j = 0; j < 16; j++) {
            float h = fmaxf(fmaf(sW1[j], s, sB1[j]), 0.f);
            z0 = fmaf(h, sW2[2 * j], z0);
            z1 = fmaf(h, sW2[2 * j + 1], z1);
        }
        z0 *= d; z1 *= d;
        g_t[i] = make_float2(z0, z1);
        g_oacc[i] = make_float2(z0, z1);  // self-loop init
    }
}

// Layer-2 scatter: oacc[col] += t[row]  (2 floats)
__global__ void k_edge_pass3(const void* __restrict__ ei) {
    int i = blockIdx.x * blockDim.x + threadIdx.x;
    if (i < N_EDGES) {
        int is64 = g_idx_is64;
        int r = load_idx(ei, i, is64);
        int c = load_idx(ei, (long long)N_EDGES + i, is64);
        float2 tv = g_t[r];
        atomicAdd(&g_oacc[c].x, tv.x);
        atomicAdd(&g_oacc[c].y, tv.y);
    }
}

// Final: scale by dinv, add b2, 2-way softmax
__global__ void k_node_c(const float* __restrict__ b2, float* __restrict__ out) {
    int i = blockIdx.x * blockDim.x + threadIdx.x;
    if (i < N_NODES) {
        float d = g_dinv[i];
        float2 a = g_oacc[i];
        float o0 = fmaf(d, a.x, b2[0]);
        float o1 = fmaf(d, a.y, b2[1]);
        float m = fmaxf(o0, o1);
        float e0 = expf(o0 - m);
        float e1 = expf(o1 - m);
        float inv = 1.f / (e0 + e1);
        out[2 * i]     = e0 * inv;
        out[2 * i + 1] = e1 * inv;
    }
}

extern "C" void kernel_launch(void* const* d_in, const int* in_sizes, int n_in,
                              void* d_out, int out_size) {
    const float* x  = (const float*)d_in[0];
    const void*  ei = d_in[1];                 // [2, N_EDGES] int32 or int64
    const float* W1 = (const float*)d_in[2];
    const float* b1 = (const float*)d_in[3];
    const float* W2 = (const float*)d_in[4];
    const float* b2 = (const float*)d_in[5];
    float* out = (float*)d_out;

    const int BT = 256;
    const int nodeGrid = (N_NODES + BT - 1) / BT;
    const int edgeGrid = (N_EDGES + BT - 1) / BT;

    k_detect<<<1, 128>>>((const int*)ei);
    k_init_deg<<<nodeGrid, BT>>>();
    k_edge_deg<<<edgeGrid, BT>>>(ei);
    k_node_a<<<nodeGrid, BT>>>(x);
    k_edge_pass2<<<edgeGrid, BT>>>(ei);
    k_node_b<<<nodeGrid, BT>>>(W1, b1, W2);
    k_edge_pass3<<<edgeGrid, BT>>>(ei);
    k_node_c<<<nodeGrid, BT>>>(b2, out);
}

// round 8
// speedup vs baseline: 1.1652x; 1.1652x over previous
#include <cuda_runtime.h>
#include <cuda_bf16.h>

#define N_NODES 250000
#define N_EDGES 5000000
#define E4 (N_EDGES / 4)     // 1,250,000
#define NN4 (N_NODES / 4)    // 62,500

// Scratch (device globals — no allocation allowed)
__device__ int    g_idx_is64;        // 1 if edge_index is int64, 0 if int32
__device__ int    g_deg[N_NODES];
__device__ float  g_dinv[N_NODES];
__device__ float  g_y[N_NODES];      // x[i] * dinv[i]
__device__ float  g_s1[N_NODES];     // layer-1 scatter accumulator
__device__ float2 g_t[N_NODES];      // per-node layer-2 message (z * dinv)
__device__ float2 g_oacc[N_NODES];   // layer-2 scatter accumulator

// ---- dtype detection: int64 edges have zero high words at odd positions ----
__global__ void k_detect(const int* __restrict__ ei32) {
    __shared__ int s_or;
    if (threadIdx.x == 0) s_or = 0;
    __syncthreads();
    int v = ei32[2 * threadIdx.x + 1];
    if (v != 0) atomicOr(&s_or, 1);
    __syncthreads();
    if (threadIdx.x == 0) g_idx_is64 = (s_or == 0) ? 1 : 0;
}

__global__ void k_init_deg() {
    int i = blockIdx.x * blockDim.x + threadIdx.x;
    if (i < NN4) ((int4*)g_deg)[i] = make_int4(0, 0, 0, 0);
}

__device__ __forceinline__ void red_f32(float* p, float v) {
    asm volatile("red.global.add.f32 [%0], %1;" :: "l"(p), "f"(v) : "memory");
}
__device__ __forceinline__ void red_v2f32(float2* p, float2 v) {
    asm volatile("red.global.add.v2.f32 [%0], {%1, %2};"
                 :: "l"(p), "f"(v.x), "f"(v.y) : "memory");
}

// Load 4 consecutive edge indices starting at element 4*idx from an index
// stream (either int32 or int64), given stream base for that half.
__device__ __forceinline__ int4 load4_idx32(const int* base, int idx) {
    return ((const int4*)base)[idx];
}
__device__ __forceinline__ int4 load4_idx64(const long long* base, int idx) {
    longlong2 a = ((const longlong2*)base)[2 * idx];
    longlong2 b = ((const longlong2*)base)[2 * idx + 1];
    return make_int4((int)a.x, (int)a.y, (int)b.x, (int)b.y);
}

// Degree pass: count in-degree from col (4 edges/thread)
__global__ void k_edge_deg(const void* __restrict__ ei) {
    int idx = blockIdx.x * blockDim.x + threadIdx.x;
    if (idx >= E4) return;
    int4 c;
    if (g_idx_is64) c = load4_idx64((const long long*)ei + N_EDGES, idx);
    else            c = load4_idx32((const int*)ei + N_EDGES, idx);
    atomicAdd(&g_deg[c.x], 1);
    atomicAdd(&g_deg[c.y], 1);
    atomicAdd(&g_deg[c.z], 1);
    atomicAdd(&g_deg[c.w], 1);
}

// Per-node (x4): dinv = rsqrt(indeg+1); y = x*dinv; s1 init with self-loop y.
__global__ void k_node_a(const float* __restrict__ x) {
    int i = blockIdx.x * blockDim.x + threadIdx.x;
    if (i >= NN4) return;
    int4   d4 = ((const int4*)g_deg)[i];
    float4 x4 = ((const float4*)x)[i];
    float4 dv, y4;
    dv.x = rsqrtf((float)(d4.x + 1));
    dv.y = rsqrtf((float)(d4.y + 1));
    dv.z = rsqrtf((float)(d4.z + 1));
    dv.w = rsqrtf((float)(d4.w + 1));
    y4.x = x4.x * dv.x; y4.y = x4.y * dv.y;
    y4.z = x4.z * dv.z; y4.w = x4.w * dv.w;
    ((float4*)g_dinv)[i] = dv;
    ((float4*)g_y)[i]    = y4;
    ((float4*)g_s1)[i]   = y4;   // self-loop; final *dinv[c] in k_node_b
}

// Layer-1 scatter: s1[col] += y[row]  (4 edges/thread)
__global__ void k_edge_pass2(const void* __restrict__ ei) {
    int idx = blockIdx.x * blockDim.x + threadIdx.x;
    if (idx >= E4) return;
    int4 r, c;
    if (g_idx_is64) {
        r = load4_idx64((const long long*)ei, idx);
        c = load4_idx64((const long long*)ei + N_EDGES, idx);
    } else {
        r = load4_idx32((const int*)ei, idx);
        c = load4_idx32((const int*)ei + N_EDGES, idx);
    }
    float yx = g_y[r.x], yy = g_y[r.y], yz = g_y[r.z], yw = g_y[r.w];
    red_f32(&g_s1[c.x], yx);
    red_f32(&g_s1[c.y], yy);
    red_f32(&g_s1[c.z], yz);
    red_f32(&g_s1[c.w], yw);
}

// Per-node MLP: s = dinv*s1 -> relu(W1*s+b1) @ W2 -> *dinv; init layer-2 acc.
__global__ void k_node_b(const float* __restrict__ W1,
                         const float* __restrict__ b1,
                         const float* __restrict__ W2) {
    __shared__ float sW1[16], sB1[16], sW2[32];
    int t = threadIdx.x;
    if (t < 16) { sW1[t] = W1[t]; sB1[t] = b1[t]; }
    else if (t < 48) { sW2[t - 16] = W2[t - 16]; }
    __syncthreads();

    int i = blockIdx.x * blockDim.x + threadIdx.x;
    if (i < N_NODES) {
        float d = g_dinv[i];
        float s = d * g_s1[i];
        float z0 = 0.f, z1 = 0.f;
        #pragma unroll
        for (int j = 0; j < 16; j++) {
            float h = fmaxf(fmaf(sW1[j], s, sB1[j]), 0.f);
            z0 = fmaf(h, sW2[2 * j], z0);
            z1 = fmaf(h, sW2[2 * j + 1], z1);
        }
        z0 *= d; z1 *= d;
        g_t[i] = make_float2(z0, z1);
        g_oacc[i] = make_float2(z0, z1);  // self-loop init
    }
}

// Layer-2 scatter: oacc[col] += t[row]  (vector RED, 4 edges/thread)
__global__ void k_edge_pass3(const void* __restrict__ ei) {
    int idx = blockIdx.x * blockDim.x + threadIdx.x;
    if (idx >= E4) return;
    int4 r, c;
    if (g_idx_is64) {
        r = load4_idx64((const long long*)ei, idx);
        c = load4_idx64((const long long*)ei + N_EDGES, idx);
    } else {
        r = load4_idx32((const int*)ei, idx);
        c = load4_idx32((const int*)ei + N_EDGES, idx);
    }
    float2 tx = g_t[r.x], ty = g_t[r.y], tz = g_t[r.z], tw = g_t[r.w];
    red_v2f32(&g_oacc[c.x], tx);
    red_v2f32(&g_oacc[c.y], ty);
    red_v2f32(&g_oacc[c.z], tz);
    red_v2f32(&g_oacc[c.w], tw);
}

// Final: scale by dinv, add b2, 2-way softmax (2 nodes/thread via float4)
__global__ void k_node_c(const float* __restrict__ b2, float* __restrict__ out) {
    int i = blockIdx.x * blockDim.x + threadIdx.x;   // pair index
    if (i >= N_NODES / 2) return;
    float bb0 = b2[0], bb1 = b2[1];
    float2 dv = ((const float2*)g_dinv)[i];
    float4 a  = ((const float4*)g_oacc)[i];   // two float2 accumulators
    float4 o;
    {
        float o0 = fmaf(dv.x, a.x, bb0);
        float o1 = fmaf(dv.x, a.y, bb1);
        float m = fmaxf(o0, o1);
        float e0 = __expf(o0 - m), e1 = __expf(o1 - m);
        float inv = __frcp_rn(e0 + e1);
        o.x = e0 * inv; o.y = e1 * inv;
    }
    {
        float o0 = fmaf(dv.y, a.z, bb0);
        float o1 = fmaf(dv.y, a.w, bb1);
        float m = fmaxf(o0, o1);
        float e0 = __expf(o0 - m), e1 = __expf(o1 - m);
        float inv = __frcp_rn(e0 + e1);
        o.z = e0 * inv; o.w = e1 * inv;
    }
    ((float4*)out)[i] = o;
}

extern "C" void kernel_launch(void* const* d_in, const int* in_sizes, int n_in,
                              void* d_out, int out_size) {
    const float* x  = (const float*)d_in[0];
    const void*  ei = d_in[1];                 // [2, N_EDGES] int32 or int64
    const float* W1 = (const float*)d_in[2];
    const float* b1 = (const float*)d_in[3];
    const float* W2 = (const float*)d_in[4];
    const float* b2 = (const float*)d_in[5];
    float* out = (float*)d_out;

    const int BT = 256;
    const int nodeGrid  = (N_NODES + BT - 1) / BT;
    const int node4Grid = (NN4 + BT - 1) / BT;
    const int pairGrid  = (N_NODES / 2 + BT - 1) / BT;
    const int edge4Grid = (E4 + BT - 1) / BT;

    k_detect<<<1, 128>>>((const int*)ei);
    k_init_deg<<<node4Grid, BT>>>();
    k_edge_deg<<<edge4Grid, BT>>>(ei);
    k_node_a<<<node4Grid, BT>>>(x);
    k_edge_pass2<<<edge4Grid, BT>>>(ei);
    k_node_b<<<nodeGrid, BT>>>(W1, b1, W2);
    k_edge_pass3<<<edge4Grid, BT>>>(ei);
    k_node_c<<<pairGrid, BT>>>(b2, out);
}